// round 11
// baseline (speedup 1.0000x reference)
#include <cuda_runtime.h>
#include <cuda_bf16.h>
#include <math.h>
#include <stdint.h>

// Problem constants
#define NN   50000
#define EE   800000
#define ET   (EE + NN)     // edges + self loops
#define FIN  512
#define HC   256           // H*C
#define HH   8
#define CCH  32
#define NCLS 40
#define MPAD 50048         // 391 * 128 (also divisible by 64: 782 * 64)

// ---------------- static device scratch ----------------
__device__ uint32_t g_h1b[(size_t)NN * 128];   // h1 as packed bf16x2 [row][128]
__device__ uint32_t g_x2h[(size_t)NN * 128];   // x2 hi bf16x2 [row][128]
__device__ uint32_t g_x2l[(size_t)NN * 128];   // x2 lo bf16x2
__device__ float g_h2[(size_t)NN * NCLS + 64]; // x2 @ W2 (padded)
__device__ float g_as1[NN * HH];
__device__ float g_ad1[NN * HH];
__device__ float g_as2[NN];
__device__ float g_ad2[NN];
__device__ int   g_deg[NN];
__device__ int   g_cursor[NN];
__device__ int   g_rowstart[NN + 1];
__device__ int   g_csr[ET];
// W1^T bf16 split
__device__ __nv_bfloat16 g_Bth[(size_t)HC * FIN];   // W1^T hi, [n][k]
__device__ __nv_bfloat16 g_Btl[(size_t)HC * FIN];   // W1^T lo
// W2^T bf16 split [n][k], n<40, k<256
__device__ __nv_bfloat16 g_W2th[40 * 256];
__device__ __nv_bfloat16 g_W2tl[40 * 256];

// ---------------- PTX helpers ----------------
__device__ __forceinline__ uint32_t smem_u32(const void* p) {
    uint32_t a;
    asm("{ .reg .u64 t; cvta.to.shared.u64 t, %1; cvt.u32.u64 %0, t; }" : "=r"(a) : "l"(p));
    return a;
}
__device__ __forceinline__ void cp16(uint32_t dst, const void* src) {
    asm volatile("cp.async.cg.shared.global [%0], [%1], 16;" :: "r"(dst), "l"(src) : "memory");
}
__device__ __forceinline__ void ldm4(uint32_t* r, uint32_t addr) {
    asm volatile("ldmatrix.sync.aligned.m8n8.x4.shared.b16 {%0,%1,%2,%3}, [%4];"
                 : "=r"(r[0]), "=r"(r[1]), "=r"(r[2]), "=r"(r[3]) : "r"(addr));
}
__device__ __forceinline__ void mma_bf16(float* c, const uint32_t* a, const uint32_t* b) {
    asm volatile(
        "mma.sync.aligned.m16n8k16.row.col.f32.bf16.bf16.f32 "
        "{%0,%1,%2,%3}, {%4,%5,%6,%7}, {%8,%9}, {%0,%1,%2,%3};"
        : "+f"(c[0]), "+f"(c[1]), "+f"(c[2]), "+f"(c[3])
        : "r"(a[0]), "r"(a[1]), "r"(a[2]), "r"(a[3]), "r"(b[0]), "r"(b[1]));
}

// ---------------- CSR build ----------------
__global__ void k_zero_deg() {
    int i = blockIdx.x * blockDim.x + threadIdx.x;
    if (i < NN) g_deg[i] = 0;
}
__global__ void k_count(const int* __restrict__ ei) {
    int i = blockIdx.x * blockDim.x + threadIdx.x;
    if (i >= ET) return;
    int dst = (i < EE) ? ei[EE + i] : (i - EE);
    atomicAdd(&g_deg[dst], 1);
}
__global__ void k_scan() {
    __shared__ int warpsums[32];
    __shared__ int carryS;
    int t = threadIdx.x, lane = t & 31, w = t >> 5;
    if (t == 0) carryS = 0;
    __syncthreads();
    for (int base = 0; base < NN; base += 4096) {
        int i0 = base + t * 4;
        int4 v = make_int4(0, 0, 0, 0);
        if (i0 + 3 < NN) {
            v = *reinterpret_cast<const int4*>(g_deg + i0);
        } else if (i0 < NN) {
            v.x = g_deg[i0];
            if (i0 + 1 < NN) v.y = g_deg[i0 + 1];
            if (i0 + 2 < NN) v.z = g_deg[i0 + 2];
        }
        int s = v.x + v.y + v.z + v.w;
        int x = s;
        #pragma unroll
        for (int o = 1; o < 32; o <<= 1) {
            int y = __shfl_up_sync(0xffffffffu, x, o);
            if (lane >= o) x += y;
        }
        if (lane == 31) warpsums[w] = x;
        __syncthreads();
        if (w == 0) {
            int ws = warpsums[lane];
            int y = ws;
            #pragma unroll
            for (int o = 1; o < 32; o <<= 1) {
                int z = __shfl_up_sync(0xffffffffu, y, o);
                if (lane >= o) y += z;
            }
            warpsums[lane] = y - ws;
        }
        __syncthreads();
        int excl = x - s + warpsums[w] + carryS;
        if (i0 < NN) {
            int p0 = excl, p1 = p0 + v.x, p2 = p1 + v.y, p3 = p2 + v.z;
            g_rowstart[i0] = p0; g_cursor[i0] = p0;
            if (i0 + 1 < NN) { g_rowstart[i0 + 1] = p1; g_cursor[i0 + 1] = p1; }
            if (i0 + 2 < NN) { g_rowstart[i0 + 2] = p2; g_cursor[i0 + 2] = p2; }
            if (i0 + 3 < NN) { g_rowstart[i0 + 3] = p3; g_cursor[i0 + 3] = p3; }
        }
        __syncthreads();
        if (t == 1023) carryS = excl + s;
        __syncthreads();
    }
    if (t == 0) g_rowstart[NN] = carryS;
}
__global__ void k_scatter(const int* __restrict__ ei) {
    int i = blockIdx.x * blockDim.x + threadIdx.x;
    if (i >= ET) return;
    int s, d;
    if (i < EE) { s = ei[i]; d = ei[EE + i]; }
    else        { s = d = i - EE; }
    int p = atomicAdd(&g_cursor[d], 1);
    g_csr[p] = s;
}

// ---------------- weight split kernels ----------------
__global__ void k_split_w(const float* __restrict__ W1) {
    int o = blockIdx.x * blockDim.x + threadIdx.x;   // [n][k]
    if (o >= HC * FIN) return;
    int n = o >> 9, k = o & 511;
    float w = W1[(size_t)k * HC + n];
    __nv_bfloat16 wh = __float2bfloat16_rn(w);
    __nv_bfloat16 wl = __float2bfloat16_rn(w - __bfloat162float(wh));
    g_Bth[o] = wh;
    g_Btl[o] = wl;
}
__global__ void k_split_w2(const float* __restrict__ W2) {
    int o = blockIdx.x * blockDim.x + threadIdx.x;   // [n][k], n<40, k<256
    if (o >= 40 * 256) return;
    int n = o >> 8, k = o & 255;
    float w = W2[(size_t)k * NCLS + n];
    __nv_bfloat16 wh = __float2bfloat16_rn(w);
    __nv_bfloat16 wl = __float2bfloat16_rn(w - __bfloat162float(wh));
    g_W2th[o] = wh;
    g_W2tl[o] = wl;
}

// ---------------- GEMM1: h1 = x @ W1, M=64 CTA (2/SM), bf16x3 HMMA + alpha1 ---
#define ROWB   80
#define AT     (64 * ROWB)      // 5120 (one A subtile, 64 rows)
#define BT     (256 * ROWB)     // 20480
#define SM_A(buf)  ((buf) * 2 * AT)
#define SM_B(buf)  (4 * AT + (buf) * 2 * BT)
#define SM_AS  (4 * AT + 4 * BT)                // 102400
#define SM_AD  (SM_AS + 1024)
#define SM_TOT (SM_AD + 1024)                   // 104448
#define NCH 16

__global__ __launch_bounds__(256, 2) void k_gemm1_mma(const float* __restrict__ x,
                                                      const float* __restrict__ a_src1,
                                                      const float* __restrict__ a_dst1) {
    extern __shared__ __align__(16) char smem[];
    uint32_t sbase = smem_u32(smem);

    int tid = threadIdx.x;
    int lane = tid & 31;
    int wid = tid >> 5;              // 0..7; head j = wid
    int wn = wid * 32;               // warp N offset
    int m0 = blockIdx.x * 64;

    *reinterpret_cast<float*>(smem + SM_AS + tid * 4) = a_src1[tid];
    *reinterpret_cast<float*>(smem + SM_AD + tid * 4) = a_dst1[tid];

    float acc[4][4][4];
    #pragma unroll
    for (int mi = 0; mi < 4; mi++)
        #pragma unroll
        for (int ni = 0; ni < 4; ni++)
            #pragma unroll
            for (int q = 0; q < 4; q++) acc[mi][ni][q] = 0.f;

    int arow = tid >> 2;             // 0..63
    int acg  = tid & 3;
    bool arow_ok = (m0 + arow) < NN;
    const float* axp = x + (size_t)(m0 + arow) * FIN + acg * 8;

    float4 st0 = make_float4(0.f, 0.f, 0.f, 0.f), st1 = st0;
    auto ldA = [&](int kc) {
        if (arow_ok) {
            st0 = *reinterpret_cast<const float4*>(axp + kc * 32);
            st1 = *reinterpret_cast<const float4*>(axp + kc * 32 + 4);
        } else {
            st0 = make_float4(0.f, 0.f, 0.f, 0.f); st1 = st0;
        }
    };
    auto stA = [&](int buf) {
        float f[8] = {st0.x, st0.y, st0.z, st0.w, st1.x, st1.y, st1.z, st1.w};
        ushort hi[8], lo[8];
        #pragma unroll
        for (int q = 0; q < 8; q++) {
            __nv_bfloat16 h = __float2bfloat16_rn(f[q]);
            __nv_bfloat16 l = __float2bfloat16_rn(f[q] - __bfloat162float(h));
            hi[q] = __bfloat16_as_ushort(h);
            lo[q] = __bfloat16_as_ushort(l);
        }
        uint4 ph, pl;
        ph.x = ((uint32_t)hi[1] << 16) | hi[0];  ph.y = ((uint32_t)hi[3] << 16) | hi[2];
        ph.z = ((uint32_t)hi[5] << 16) | hi[4];  ph.w = ((uint32_t)hi[7] << 16) | hi[6];
        pl.x = ((uint32_t)lo[1] << 16) | lo[0];  pl.y = ((uint32_t)lo[3] << 16) | lo[2];
        pl.z = ((uint32_t)lo[5] << 16) | lo[4];  pl.w = ((uint32_t)lo[7] << 16) | lo[6];
        uint32_t off = SM_A(buf) + arow * ROWB + acg * 16;
        *reinterpret_cast<uint4*>(smem + off)      = ph;
        *reinterpret_cast<uint4*>(smem + off + AT) = pl;
    };
    auto ldB = [&](int buf, int kc) {
        #pragma unroll
        for (int i = 0; i < 8; i++) {
            int idx = tid + i * 256;
            int til = idx >> 10;
            int row = (idx & 1023) >> 2;
            int c   = idx & 3;
            const __nv_bfloat16* src = (til ? g_Btl : g_Bth) + ((size_t)row * FIN + kc * 32 + c * 8);
            cp16(sbase + SM_B(buf) + til * BT + row * ROWB + c * 16, src);
        }
    };

    // prologue: buf0 <- chunk0; regs <- chunk1
    ldA(0); stA(0); ldB(0, 0);
    asm volatile("cp.async.commit_group;" ::: "memory");
    ldA(1);

    #pragma unroll 1
    for (int c = 0; c < NCH; c++) {
        int buf = c & 1;
        asm volatile("cp.async.wait_group 0;" ::: "memory");
        __syncthreads();

        // issue next chunk's tile fills BEFORE this chunk's MMAs (overlap)
        if (c + 1 < NCH) {
            stA(buf ^ 1);
            ldB(buf ^ 1, c + 1);
            asm volatile("cp.async.commit_group;" ::: "memory");
            if (c + 2 < NCH) ldA(c + 2);
        }

        uint32_t aH = sbase + SM_A(buf);
        uint32_t bH = sbase + SM_B(buf);
        #pragma unroll
        for (int kk = 0; kk < 2; kk++) {
            uint32_t af[4][4], bfh[4][2], bfl[4][2];
            uint32_t kbA = kk * 32 + (lane >> 4) * 16;
            uint32_t kbB = kk * 32 + ((lane >> 3) & 1) * 16;
            #pragma unroll
            for (int mi = 0; mi < 4; mi++)
                ldm4(af[mi], aH + (uint32_t)(mi * 16 + (lane & 15)) * ROWB + kbA);
            #pragma unroll
            for (int nb2 = 0; nb2 < 2; nb2++) {
                uint32_t rowb = wn + nb2 * 16 + (lane & 7) + ((lane >> 4) << 3);
                uint32_t r[4];
                ldm4(r, bH + rowb * ROWB + kbB);
                bfh[nb2 * 2][0] = r[0]; bfh[nb2 * 2][1] = r[1];
                bfh[nb2 * 2 + 1][0] = r[2]; bfh[nb2 * 2 + 1][1] = r[3];
            }
            #pragma unroll
            for (int mi = 0; mi < 4; mi++)
                #pragma unroll
                for (int nb = 0; nb < 4; nb++)
                    mma_bf16(acc[mi][nb], af[mi], bfh[nb]);
            #pragma unroll
            for (int nb2 = 0; nb2 < 2; nb2++) {
                uint32_t rowb = wn + nb2 * 16 + (lane & 7) + ((lane >> 4) << 3);
                uint32_t r[4];
                ldm4(r, bH + BT + rowb * ROWB + kbB);
                bfl[nb2 * 2][0] = r[0]; bfl[nb2 * 2][1] = r[1];
                bfl[nb2 * 2 + 1][0] = r[2]; bfl[nb2 * 2 + 1][1] = r[3];
            }
            #pragma unroll
            for (int mi = 0; mi < 4; mi++)
                #pragma unroll
                for (int nb = 0; nb < 4; nb++)
                    mma_bf16(acc[mi][nb], af[mi], bfl[nb]);
            #pragma unroll
            for (int mi = 0; mi < 4; mi++)
                ldm4(af[mi], aH + AT + (uint32_t)(mi * 16 + (lane & 15)) * ROWB + kbA);
            #pragma unroll
            for (int mi = 0; mi < 4; mi++)
                #pragma unroll
                for (int nb = 0; nb < 4; nb++)
                    mma_bf16(acc[mi][nb], af[mi], bfh[nb]);
        }
    }

    int j = wid;                     // head index
    const float* asS = reinterpret_cast<const float*>(smem + SM_AS);
    const float* adS = reinterpret_cast<const float*>(smem + SM_AD);
    float asv[4][2], adv[4][2];
    #pragma unroll
    for (int nb = 0; nb < 4; nb++) {
        int col = wn + nb * 8 + (lane & 3) * 2;
        asv[nb][0] = asS[col];     asv[nb][1] = asS[col + 1];
        adv[nb][0] = adS[col];     adv[nb][1] = adS[col + 1];
    }

    #pragma unroll
    for (int mi = 0; mi < 4; mi++) {
        int row0 = m0 + mi * 16 + (lane >> 2);
        float s0 = 0.f, d0 = 0.f, s1 = 0.f, d1 = 0.f;
        #pragma unroll
        for (int nb = 0; nb < 4; nb++) {
            s0 += acc[mi][nb][0] * asv[nb][0] + acc[mi][nb][1] * asv[nb][1];
            d0 += acc[mi][nb][0] * adv[nb][0] + acc[mi][nb][1] * adv[nb][1];
            s1 += acc[mi][nb][2] * asv[nb][0] + acc[mi][nb][3] * asv[nb][1];
            d1 += acc[mi][nb][2] * adv[nb][0] + acc[mi][nb][3] * adv[nb][1];
        }
        #pragma unroll
        for (int o = 1; o < 4; o <<= 1) {
            s0 += __shfl_xor_sync(0xffffffffu, s0, o);
            d0 += __shfl_xor_sync(0xffffffffu, d0, o);
            s1 += __shfl_xor_sync(0xffffffffu, s1, o);
            d1 += __shfl_xor_sync(0xffffffffu, d1, o);
        }
        if ((lane & 3) == 0) {
            if (row0 < NN)     { g_as1[row0 * 8 + j] = s0;       g_ad1[row0 * 8 + j] = d0; }
            if (row0 + 8 < NN) { g_as1[(row0 + 8) * 8 + j] = s1; g_ad1[(row0 + 8) * 8 + j] = d1; }
        }
        #pragma unroll
        for (int nb = 0; nb < 4; nb++) {
            uint32_t gidx = (uint32_t)(wn >> 1) + nb * 4 + (lane & 3);
            __nv_bfloat162 p0 = __float22bfloat162_rn(make_float2(acc[mi][nb][0], acc[mi][nb][1]));
            __nv_bfloat162 p1 = __float22bfloat162_rn(make_float2(acc[mi][nb][2], acc[mi][nb][3]));
            if (row0 < NN)
                g_h1b[(size_t)row0 * 128 + gidx] = *reinterpret_cast<uint32_t*>(&p0);
            if (row0 + 8 < NN)
                g_h1b[(size_t)(row0 + 8) * 128 + gidx] = *reinterpret_cast<uint32_t*>(&p1);
        }
    }
}

// ---------------- layer-1 aggregation: branchless softmax, 4-edge batched -----
__global__ __launch_bounds__(256) void k_agg1(const float* __restrict__ b1) {
    int warp = (blockIdx.x * blockDim.x + threadIdx.x) >> 5;
    int lane = threadIdx.x & 31;
    if (warp >= NN) return;
    int d = warp;
    int s0 = g_rowstart[d], s1 = g_rowstart[d + 1];
    float adv = (lane < HH) ? g_ad1[d * HH + lane] : 0.f;
    int hs = lane >> 4;

    float den = 0.f;
    float2 acc[4];
    #pragma unroll
    for (int t = 0; t < 4; t++) acc[t] = make_float2(0.f, 0.f);

    int i = s0;
    for (; i + 4 <= s1; i += 4) {
        int e0 = g_csr[i], e1 = g_csr[i + 1], e2 = g_csr[i + 2], e3 = g_csr[i + 3];
        float p0 = 0.f, p1 = 0.f, p2 = 0.f, p3 = 0.f;
        if (lane < HH) {
            float v0 = g_as1[e0 * HH + lane] + adv;
            float v1 = g_as1[e1 * HH + lane] + adv;
            float v2 = g_as1[e2 * HH + lane] + adv;
            float v3 = g_as1[e3 * HH + lane] + adv;
            v0 = (v0 > 0.f) ? v0 : 0.2f * v0;  p0 = __expf(v0);
            v1 = (v1 > 0.f) ? v1 : 0.2f * v1;  p1 = __expf(v1);
            v2 = (v2 > 0.f) ? v2 : 0.2f * v2;  p2 = __expf(v2);
            v3 = (v3 > 0.f) ? v3 : 0.2f * v3;  p3 = __expf(v3);
            den += p0 + p1 + p2 + p3;
        }
        const uint32_t* r0 = g_h1b + (size_t)e0 * 128;
        const uint32_t* r1 = g_h1b + (size_t)e1 * 128;
        const uint32_t* r2 = g_h1b + (size_t)e2 * 128;
        const uint32_t* r3 = g_h1b + (size_t)e3 * 128;
        uint32_t u0[4], u1[4], u2[4], u3[4];
        #pragma unroll
        for (int t = 0; t < 4; t++) {
            u0[t] = r0[t * 32 + lane];
            u1[t] = r1[t * 32 + lane];
            u2[t] = r2[t * 32 + lane];
            u3[t] = r3[t * 32 + lane];
        }
        #pragma unroll
        for (int t = 0; t < 4; t++) {
            int sl = 2 * t + hs;
            float q0 = __shfl_sync(0xffffffffu, p0, sl);
            float q1 = __shfl_sync(0xffffffffu, p1, sl);
            float q2 = __shfl_sync(0xffffffffu, p2, sl);
            float q3 = __shfl_sync(0xffffffffu, p3, sl);
            float2 f0 = __bfloat1622float2(*reinterpret_cast<__nv_bfloat162*>(&u0[t]));
            float2 f1 = __bfloat1622float2(*reinterpret_cast<__nv_bfloat162*>(&u1[t]));
            float2 f2 = __bfloat1622float2(*reinterpret_cast<__nv_bfloat162*>(&u2[t]));
            float2 f3 = __bfloat1622float2(*reinterpret_cast<__nv_bfloat162*>(&u3[t]));
            acc[t].x += q0 * f0.x + q1 * f1.x + q2 * f2.x + q3 * f3.x;
            acc[t].y += q0 * f0.y + q1 * f1.y + q2 * f2.y + q3 * f3.y;
        }
    }
    for (; i < s1; i++) {
        int src = g_csr[i];
        float p = 0.f;
        if (lane < HH) {
            float v = g_as1[src * HH + lane] + adv;
            v = (v > 0.f) ? v : 0.2f * v;
            p = __expf(v);
            den += p;
        }
        const uint32_t* hr = g_h1b + (size_t)src * 128;
        #pragma unroll
        for (int t = 0; t < 4; t++) {
            float pj = __shfl_sync(0xffffffffu, p, 2 * t + hs);
            uint32_t u = hr[t * 32 + lane];
            float2 hf = __bfloat1622float2(*reinterpret_cast<__nv_bfloat162*>(&u));
            acc[t].x += pj * hf.x;
            acc[t].y += pj * hf.y;
        }
    }
    #pragma unroll
    for (int t = 0; t < 4; t++) {
        float dd = __shfl_sync(0xffffffffu, den, 2 * t + hs);
        float inv = 1.f / (dd + 1e-16f);
        int col = 64 * t + 2 * lane;
        float v0 = acc[t].x * inv + __ldg(b1 + col);
        float v1 = acc[t].y * inv + __ldg(b1 + col + 1);
        v0 = (v0 > 0.f) ? v0 : (__expf(v0) - 1.f);
        v1 = (v1 > 0.f) ? v1 : (__expf(v1) - 1.f);
        __nv_bfloat16 h0 = __float2bfloat16_rn(v0);
        __nv_bfloat16 h1 = __float2bfloat16_rn(v1);
        __nv_bfloat16 l0 = __float2bfloat16_rn(v0 - __bfloat162float(h0));
        __nv_bfloat16 l1 = __float2bfloat16_rn(v1 - __bfloat162float(h1));
        uint32_t wh = ((uint32_t)__bfloat16_as_ushort(h1) << 16) | __bfloat16_as_ushort(h0);
        uint32_t wl = ((uint32_t)__bfloat16_as_ushort(l1) << 16) | __bfloat16_as_ushort(l0);
        g_x2h[(size_t)d * 128 + 32 * t + lane] = wh;
        g_x2l[(size_t)d * 128 + 32 * t + lane] = wl;
    }
}

// ---------------- GEMM2: h2 = x2 @ W2 via bf16x3 HMMA, fused alpha2 -----------
#define G2_ROWB 80
#define G2_AT   (128 * G2_ROWB)   // 10240
#define G2_BT   (48 * G2_ROWB)    // 3840
#define SM2_A(buf) ((buf) * 2 * G2_AT)
#define SM2_B(buf) (4 * G2_AT + (buf) * 2 * G2_BT)
#define SM2_AS  (4 * G2_AT + 4 * G2_BT)      // 56320
#define SM2_AD  (SM2_AS + 256)
#define SM2_TOT (SM2_AD + 256)               // 56832
#define G2_NCH 8   // K=256, chunks of 32

__global__ __launch_bounds__(256) void k_gemm2_mma(const float* __restrict__ a_src2,
                                                   const float* __restrict__ a_dst2) {
    extern __shared__ __align__(16) char smem[];
    uint32_t sbase = smem_u32(smem);

    int tid = threadIdx.x;
    int lane = tid & 31;
    int wid = tid >> 5;
    int wm = wid * 16;
    int m0 = blockIdx.x * 128;

    if (tid < NCLS) {
        *reinterpret_cast<float*>(smem + SM2_AS + tid * 4) = a_src2[tid];
        *reinterpret_cast<float*>(smem + SM2_AD + tid * 4) = a_dst2[tid];
    }

    float acc[5][4];
    #pragma unroll
    for (int nb = 0; nb < 5; nb++)
        #pragma unroll
        for (int q = 0; q < 4; q++) acc[nb][q] = 0.f;

    auto ldAB = [&](int buf, int kc) {
        #pragma unroll
        for (int i = 0; i < 4; i++) {
            int idx = tid + i * 256;
            int til = idx >> 9;
            int rem = idx & 511;
            int row = rem >> 2;
            int c   = rem & 3;
            if (m0 + row < NN) {
                const uint32_t* src = (til ? g_x2l : g_x2h) + (size_t)(m0 + row) * 128 + kc * 16 + c * 4;
                cp16(sbase + SM2_A(buf) + til * G2_AT + row * G2_ROWB + c * 16, src);
            }
        }
        #pragma unroll
        for (int i = 0; i < 2; i++) {
            int idx = tid + i * 256;
            if (idx < 320) {
                int til = idx / 160;
                int rem = idx % 160;
                int row = rem >> 2;
                int c   = rem & 3;
                const __nv_bfloat16* src = (til ? g_W2tl : g_W2th) + (size_t)row * 256 + kc * 32 + c * 8;
                cp16(sbase + SM2_B(buf) + til * G2_BT + row * G2_ROWB + c * 16, src);
            }
        }
    };

    ldAB(0, 0);
    asm volatile("cp.async.commit_group;" ::: "memory");

    #pragma unroll 1
    for (int c = 0; c < G2_NCH; c++) {
        int buf = c & 1;
        if (c + 1 < G2_NCH) {
            ldAB(buf ^ 1, c + 1);
            asm volatile("cp.async.commit_group;" ::: "memory");
            asm volatile("cp.async.wait_group 1;" ::: "memory");
        } else {
            asm volatile("cp.async.wait_group 0;" ::: "memory");
        }
        __syncthreads();

        uint32_t aH = sbase + SM2_A(buf);
        uint32_t bH = sbase + SM2_B(buf);
        #pragma unroll
        for (int kk = 0; kk < 2; kk++) {
            uint32_t af[4], bfh[6][2], bfl[6][2];
            uint32_t kbA = kk * 32 + (lane >> 4) * 16;
            uint32_t kbB = kk * 32 + ((lane >> 3) & 1) * 16;
            ldm4(af, aH + (uint32_t)(wm + (lane & 15)) * G2_ROWB + kbA);
            #pragma unroll
            for (int g = 0; g < 3; g++) {
                uint32_t rowb = g * 16 + (lane & 7) + ((lane >> 4) << 3);
                uint32_t r[4];
                ldm4(r, bH + rowb * G2_ROWB + kbB);
                bfh[g * 2][0] = r[0]; bfh[g * 2][1] = r[1];
                bfh[g * 2 + 1][0] = r[2]; bfh[g * 2 + 1][1] = r[3];
            }
            #pragma unroll
            for (int nb = 0; nb < 5; nb++)
                mma_bf16(acc[nb], af, bfh[nb]);
            #pragma unroll
            for (int g = 0; g < 3; g++) {
                uint32_t rowb = g * 16 + (lane & 7) + ((lane >> 4) << 3);
                uint32_t r[4];
                ldm4(r, bH + G2_BT + rowb * G2_ROWB + kbB);
                bfl[g * 2][0] = r[0]; bfl[g * 2][1] = r[1];
                bfl[g * 2 + 1][0] = r[2]; bfl[g * 2 + 1][1] = r[3];
            }
            #pragma unroll
            for (int nb = 0; nb < 5; nb++)
                mma_bf16(acc[nb], af, bfl[nb]);
            ldm4(af, aH + G2_AT + (uint32_t)(wm + (lane & 15)) * G2_ROWB + kbA);
            #pragma unroll
            for (int nb = 0; nb < 5; nb++)
                mma_bf16(acc[nb], af, bfh[nb]);
        }
        __syncthreads();
    }

    const float* asS = reinterpret_cast<const float*>(smem + SM2_AS);
    const float* adS = reinterpret_cast<const float*>(smem + SM2_AD);
    float s0 = 0.f, d0 = 0.f, s1 = 0.f, d1 = 0.f;
    #pragma unroll
    for (int nb = 0; nb < 5; nb++) {
        int col = nb * 8 + (lane & 3) * 2;
        float a0 = asS[col], a1 = asS[col + 1];
        float q0 = adS[col], q1 = adS[col + 1];
        s0 += acc[nb][0] * a0 + acc[nb][1] * a1;
        d0 += acc[nb][0] * q0 + acc[nb][1] * q1;
        s1 += acc[nb][2] * a0 + acc[nb][3] * a1;
        d1 += acc[nb][2] * q0 + acc[nb][3] * q1;
    }
    #pragma unroll
    for (int o = 1; o < 4; o <<= 1) {
        s0 += __shfl_xor_sync(0xffffffffu, s0, o);
        d0 += __shfl_xor_sync(0xffffffffu, d0, o);
        s1 += __shfl_xor_sync(0xffffffffu, s1, o);
        d1 += __shfl_xor_sync(0xffffffffu, d1, o);
    }
    int r0 = m0 + wm + (lane >> 2);
    int r1 = r0 + 8;
    if ((lane & 3) == 0) {
        if (r0 < NN) { g_as2[r0] = s0; g_ad2[r0] = d0; }
        if (r1 < NN) { g_as2[r1] = s1; g_ad2[r1] = d1; }
    }
    #pragma unroll
    for (int nb = 0; nb < 5; nb++) {
        int col = nb * 8 + (lane & 3) * 2;
        if (r0 < NN)
            *reinterpret_cast<float2*>(g_h2 + (size_t)r0 * NCLS + col) = make_float2(acc[nb][0], acc[nb][1]);
        if (r1 < NN)
            *reinterpret_cast<float2*>(g_h2 + (size_t)r1 * NCLS + col) = make_float2(acc[nb][2], acc[nb][3]);
    }
}

// ---------------- layer-2 aggregation + log_softmax, 4-edge batched -----------
__global__ __launch_bounds__(256) void k_agg2(const float* __restrict__ b2,
                                              float* __restrict__ out) {
    int warp = (blockIdx.x * blockDim.x + threadIdx.x) >> 5;
    int lane = threadIdx.x & 31;
    if (warp >= NN) return;
    int d = warp;
    int s0 = g_rowstart[d], s1 = g_rowstart[d + 1];
    float adv = g_ad2[d];

    float den = 0.f, a0 = 0.f, a1 = 0.f;
    int i = s0;
    for (; i + 4 <= s1; i += 4) {
        int e0 = g_csr[i], e1 = g_csr[i + 1], e2 = g_csr[i + 2], e3 = g_csr[i + 3];
        float v0 = g_as2[e0] + adv, v1 = g_as2[e1] + adv;
        float v2 = g_as2[e2] + adv, v3 = g_as2[e3] + adv;
        v0 = (v0 > 0.f) ? v0 : 0.2f * v0;  float p0 = __expf(v0);
        v1 = (v1 > 0.f) ? v1 : 0.2f * v1;  float p1 = __expf(v1);
        v2 = (v2 > 0.f) ? v2 : 0.2f * v2;  float p2 = __expf(v2);
        v3 = (v3 > 0.f) ? v3 : 0.2f * v3;  float p3 = __expf(v3);
        den += p0 + p1 + p2 + p3;
        const float* r0 = g_h2 + (size_t)e0 * NCLS;
        const float* r1 = g_h2 + (size_t)e1 * NCLS;
        const float* r2 = g_h2 + (size_t)e2 * NCLS;
        const float* r3 = g_h2 + (size_t)e3 * NCLS;
        float h00 = r0[lane], h01 = r0[32 + lane];
        float h10 = r1[lane], h11 = r1[32 + lane];
        float h20 = r2[lane], h21 = r2[32 + lane];
        float h30 = r3[lane], h31 = r3[32 + lane];
        a0 += p0 * h00 + p1 * h10 + p2 * h20 + p3 * h30;
        a1 += p0 * h01 + p1 * h11 + p2 * h21 + p3 * h31;
    }
    for (; i < s1; i++) {
        int src = g_csr[i];
        float v = g_as2[src] + adv;
        float e = (v > 0.f) ? v : 0.2f * v;
        float p = __expf(e);
        den += p;
        const float* hr = g_h2 + (size_t)src * NCLS;
        a0 += p * hr[lane];
        a1 += p * hr[32 + lane];
    }
    float inv = 1.f / (den + 1e-16f);
    float v0 = a0 * inv + b2[lane];
    float v1 = -3.0e38f;
    if (lane < 8) v1 = a1 * inv + b2[32 + lane];

    float mx = fmaxf(v0, v1);
    #pragma unroll
    for (int o = 16; o; o >>= 1) mx = fmaxf(mx, __shfl_xor_sync(0xffffffffu, mx, o));
    float se = __expf(v0 - mx) + ((lane < 8) ? __expf(v1 - mx) : 0.f);
    #pragma unroll
    for (int o = 16; o; o >>= 1) se += __shfl_xor_sync(0xffffffffu, se, o);
    float lse = mx + __logf(se);

    out[(size_t)d * NCLS + lane] = v0 - lse;
    if (lane < 8) out[(size_t)d * NCLS + 32 + lane] = v1 - lse;
}

// ---------------- launch ----------------
extern "C" void kernel_launch(void* const* d_in, const int* in_sizes, int n_in,
                              void* d_out, int out_size) {
    const float* x       = (const float*)d_in[0];
    const int*   ei      = (const int*)  d_in[1];
    const float* W1      = (const float*)d_in[2];
    const float* a_src1  = (const float*)d_in[3];
    const float* a_dst1  = (const float*)d_in[4];
    const float* b1      = (const float*)d_in[5];
    const float* W2      = (const float*)d_in[6];
    const float* a_src2  = (const float*)d_in[7];
    const float* a_dst2  = (const float*)d_in[8];
    const float* b2      = (const float*)d_in[9];
    float* out = (float*)d_out;

    cudaFuncSetAttribute(k_gemm1_mma, cudaFuncAttributeMaxDynamicSharedMemorySize, SM_TOT);
    cudaFuncSetAttribute(k_gemm2_mma, cudaFuncAttributeMaxDynamicSharedMemorySize, SM2_TOT);

    // order chosen so the profiled launch slot (#4) is gemm1
    k_split_w<<<(HC * FIN + 255) / 256, 256>>>(W1);                          // 1
    k_zero_deg<<<(NN + 255) / 256, 256>>>();                                 // 2
    k_count<<<(ET + 255) / 256, 256>>>(ei);                                  // 3
    k_gemm1_mma<<<MPAD / 64, 256, SM_TOT>>>(x, a_src1, a_dst1);              // 4
    k_split_w2<<<(40 * 256 + 255) / 256, 256>>>(W2);                         // 5
    k_scan<<<1, 1024>>>();                                                   // 6
    k_scatter<<<(ET + 255) / 256, 256>>>(ei);                                // 7
    k_agg1<<<(NN * 32 + 255) / 256, 256>>>(b1);                              // 8
    k_gemm2_mma<<<MPAD / 128, 256, SM2_TOT>>>(a_src2, a_dst2);               // 9
    k_agg2<<<(NN * 32 + 255) / 256, 256>>>(b2, out);                         // 10
}

// round 12
// speedup vs baseline: 1.1654x; 1.1654x over previous
#include <cuda_runtime.h>
#include <cuda_bf16.h>
#include <math.h>
#include <stdint.h>

// Problem constants
#define NN   50000
#define EE   800000
#define ET   (EE + NN)     // edges + self loops
#define FIN  512
#define HC   256           // H*C
#define HH   8
#define CCH  32
#define NCLS 40
#define MPAD 50048         // 782 * 64

// ---------------- static device scratch ----------------
__device__ uint32_t g_h1b[(size_t)NN * 128];   // h1 as packed bf16x2 [row][128]
__device__ uint32_t g_x2h[(size_t)NN * 128];   // x2 hi bf16x2 [row][128]
__device__ uint32_t g_x2l[(size_t)NN * 128];   // x2 lo bf16x2
__device__ float g_h2[(size_t)NN * NCLS + 64]; // x2 @ W2 (padded)
__device__ float g_as1[NN * HH];
__device__ float g_ad1[NN * HH];
__device__ float g_as2[NN];
__device__ float g_ad2[NN];
__device__ int   g_deg[NN];
__device__ int   g_cursor[NN];
__device__ int   g_rowstart[NN + 1];
__device__ int   g_csr[ET];
// W1^T bf16 (hi only needed now)
__device__ __nv_bfloat16 g_Bth[(size_t)HC * FIN];   // W1^T hi, [n][k]
// W2^T bf16 hi [n][k], n<40, k<256
__device__ __nv_bfloat16 g_W2th[40 * 256];

// ---------------- PTX helpers ----------------
__device__ __forceinline__ uint32_t smem_u32(const void* p) {
    uint32_t a;
    asm("{ .reg .u64 t; cvta.to.shared.u64 t, %1; cvt.u32.u64 %0, t; }" : "=r"(a) : "l"(p));
    return a;
}
__device__ __forceinline__ void cp16(uint32_t dst, const void* src) {
    asm volatile("cp.async.cg.shared.global [%0], [%1], 16;" :: "r"(dst), "l"(src) : "memory");
}
__device__ __forceinline__ void ldm4(uint32_t* r, uint32_t addr) {
    asm volatile("ldmatrix.sync.aligned.m8n8.x4.shared.b16 {%0,%1,%2,%3}, [%4];"
                 : "=r"(r[0]), "=r"(r[1]), "=r"(r[2]), "=r"(r[3]) : "r"(addr));
}
__device__ __forceinline__ void mma_bf16(float* c, const uint32_t* a, const uint32_t* b) {
    asm volatile(
        "mma.sync.aligned.m16n8k16.row.col.f32.bf16.bf16.f32 "
        "{%0,%1,%2,%3}, {%4,%5,%6,%7}, {%8,%9}, {%0,%1,%2,%3};"
        : "+f"(c[0]), "+f"(c[1]), "+f"(c[2]), "+f"(c[3])
        : "r"(a[0]), "r"(a[1]), "r"(a[2]), "r"(a[3]), "r"(b[0]), "r"(b[1]));
}

// ---------------- CSR build ----------------
__global__ void k_zero_deg() {
    int i = blockIdx.x * blockDim.x + threadIdx.x;
    if (i < NN) g_deg[i] = 0;
}
__global__ void k_count(const int* __restrict__ ei) {
    int i = blockIdx.x * blockDim.x + threadIdx.x;
    if (i >= ET) return;
    int dst = (i < EE) ? ei[EE + i] : (i - EE);
    atomicAdd(&g_deg[dst], 1);
}
__global__ void k_scan() {
    __shared__ int warpsums[32];
    __shared__ int carryS;
    int t = threadIdx.x, lane = t & 31, w = t >> 5;
    if (t == 0) carryS = 0;
    __syncthreads();
    for (int base = 0; base < NN; base += 4096) {
        int i0 = base + t * 4;
        int4 v = make_int4(0, 0, 0, 0);
        if (i0 + 3 < NN) {
            v = *reinterpret_cast<const int4*>(g_deg + i0);
        } else if (i0 < NN) {
            v.x = g_deg[i0];
            if (i0 + 1 < NN) v.y = g_deg[i0 + 1];
            if (i0 + 2 < NN) v.z = g_deg[i0 + 2];
        }
        int s = v.x + v.y + v.z + v.w;
        int x = s;
        #pragma unroll
        for (int o = 1; o < 32; o <<= 1) {
            int y = __shfl_up_sync(0xffffffffu, x, o);
            if (lane >= o) x += y;
        }
        if (lane == 31) warpsums[w] = x;
        __syncthreads();
        if (w == 0) {
            int ws = warpsums[lane];
            int y = ws;
            #pragma unroll
            for (int o = 1; o < 32; o <<= 1) {
                int z = __shfl_up_sync(0xffffffffu, y, o);
                if (lane >= o) y += z;
            }
            warpsums[lane] = y - ws;
        }
        __syncthreads();
        int excl = x - s + warpsums[w] + carryS;
        if (i0 < NN) {
            int p0 = excl, p1 = p0 + v.x, p2 = p1 + v.y, p3 = p2 + v.z;
            g_rowstart[i0] = p0; g_cursor[i0] = p0;
            if (i0 + 1 < NN) { g_rowstart[i0 + 1] = p1; g_cursor[i0 + 1] = p1; }
            if (i0 + 2 < NN) { g_rowstart[i0 + 2] = p2; g_cursor[i0 + 2] = p2; }
            if (i0 + 3 < NN) { g_rowstart[i0 + 3] = p3; g_cursor[i0 + 3] = p3; }
        }
        __syncthreads();
        if (t == 1023) carryS = excl + s;
        __syncthreads();
    }
    if (t == 0) g_rowstart[NN] = carryS;
}
__global__ void k_scatter(const int* __restrict__ ei) {
    int i = blockIdx.x * blockDim.x + threadIdx.x;
    if (i >= ET) return;
    int s, d;
    if (i < EE) { s = ei[i]; d = ei[EE + i]; }
    else        { s = d = i - EE; }
    int p = atomicAdd(&g_cursor[d], 1);
    g_csr[p] = s;
}

// ---------------- weight split kernels (hi only) ----------------
__global__ void k_split_w(const float* __restrict__ W1) {
    int o = blockIdx.x * blockDim.x + threadIdx.x;   // [n][k]
    if (o >= HC * FIN) return;
    int n = o >> 9, k = o & 511;
    g_Bth[o] = __float2bfloat16_rn(W1[(size_t)k * HC + n]);
}
__global__ void k_split_w2(const float* __restrict__ W2) {
    int o = blockIdx.x * blockDim.x + threadIdx.x;   // [n][k], n<40, k<256
    if (o >= 40 * 256) return;
    int n = o >> 8, k = o & 255;
    g_W2th[o] = __float2bfloat16_rn(W2[(size_t)k * NCLS + n]);
}

// ---------------- GEMM1: h1 = x @ W1, bf16x2 (exact-A) HMMA + fused alpha1 ----
#define ROWB   80
#define AT     (64 * ROWB)      // 5120 (one A subtile, 64 rows)
#define BT     (256 * ROWB)     // 20480 (B hi tile)
#define SM_A(buf)  ((buf) * 2 * AT)            // Ah at +0, Al at +AT
#define SM_B(buf)  (4 * AT + (buf) * BT)       // hi only
#define SM_AS  (4 * AT + 2 * BT)               // 61440
#define SM_AD  (SM_AS + 1024)
#define SM_TOT (SM_AD + 1024)                  // 63488
#define NCH 16

__global__ __launch_bounds__(256, 2) void k_gemm1_mma(const float* __restrict__ x,
                                                      const float* __restrict__ a_src1,
                                                      const float* __restrict__ a_dst1) {
    extern __shared__ __align__(16) char smem[];
    uint32_t sbase = smem_u32(smem);

    int tid = threadIdx.x;
    int lane = tid & 31;
    int wid = tid >> 5;              // 0..7; head j = wid
    int wn = wid * 32;               // warp N offset
    int m0 = blockIdx.x * 64;

    *reinterpret_cast<float*>(smem + SM_AS + tid * 4) = a_src1[tid];
    *reinterpret_cast<float*>(smem + SM_AD + tid * 4) = a_dst1[tid];

    float acc[4][4][4];
    #pragma unroll
    for (int mi = 0; mi < 4; mi++)
        #pragma unroll
        for (int ni = 0; ni < 4; ni++)
            #pragma unroll
            for (int q = 0; q < 4; q++) acc[mi][ni][q] = 0.f;

    int arow = tid >> 2;             // 0..63
    int acg  = tid & 3;
    bool arow_ok = (m0 + arow) < NN;
    const float* axp = x + (size_t)(m0 + arow) * FIN + acg * 8;

    float4 st0 = make_float4(0.f, 0.f, 0.f, 0.f), st1 = st0;
    auto ldA = [&](int kc) {
        if (arow_ok) {
            st0 = *reinterpret_cast<const float4*>(axp + kc * 32);
            st1 = *reinterpret_cast<const float4*>(axp + kc * 32 + 4);
        } else {
            st0 = make_float4(0.f, 0.f, 0.f, 0.f); st1 = st0;
        }
    };
    auto stA = [&](int buf) {
        float f[8] = {st0.x, st0.y, st0.z, st0.w, st1.x, st1.y, st1.z, st1.w};
        ushort hi[8], lo[8];
        #pragma unroll
        for (int q = 0; q < 8; q++) {
            __nv_bfloat16 h = __float2bfloat16_rn(f[q]);
            __nv_bfloat16 l = __float2bfloat16_rn(f[q] - __bfloat162float(h));
            hi[q] = __bfloat16_as_ushort(h);
            lo[q] = __bfloat16_as_ushort(l);
        }
        uint4 ph, pl;
        ph.x = ((uint32_t)hi[1] << 16) | hi[0];  ph.y = ((uint32_t)hi[3] << 16) | hi[2];
        ph.z = ((uint32_t)hi[5] << 16) | hi[4];  ph.w = ((uint32_t)hi[7] << 16) | hi[6];
        pl.x = ((uint32_t)lo[1] << 16) | lo[0];  pl.y = ((uint32_t)lo[3] << 16) | lo[2];
        pl.z = ((uint32_t)lo[5] << 16) | lo[4];  pl.w = ((uint32_t)lo[7] << 16) | lo[6];
        uint32_t off = SM_A(buf) + arow * ROWB + acg * 16;
        *reinterpret_cast<uint4*>(smem + off)      = ph;
        *reinterpret_cast<uint4*>(smem + off + AT) = pl;
    };
    auto ldB = [&](int buf, int kc) {
        #pragma unroll
        for (int i = 0; i < 4; i++) {
            int idx = tid + i * 256;       // 1024 cp16 total (hi only)
            int row = idx >> 2;
            int c   = idx & 3;
            const __nv_bfloat16* src = g_Bth + ((size_t)row * FIN + kc * 32 + c * 8);
            cp16(sbase + SM_B(buf) + row * ROWB + c * 16, src);
        }
    };

    // prologue: buf0 <- chunk0; regs <- chunk1
    ldA(0); stA(0); ldB(0, 0);
    asm volatile("cp.async.commit_group;" ::: "memory");
    ldA(1);

    #pragma unroll 1
    for (int c = 0; c < NCH; c++) {
        int buf = c & 1;
        asm volatile("cp.async.wait_group 0;" ::: "memory");
        __syncthreads();

        if (c + 1 < NCH) {
            stA(buf ^ 1);
            ldB(buf ^ 1, c + 1);
            asm volatile("cp.async.commit_group;" ::: "memory");
            if (c + 2 < NCH) ldA(c + 2);
        }

        uint32_t aH = sbase + SM_A(buf);
        uint32_t bH = sbase + SM_B(buf);
        #pragma unroll
        for (int kk = 0; kk < 2; kk++) {
            uint32_t af[4][4], bfh[4][2];
            uint32_t kbA = kk * 32 + (lane >> 4) * 16;
            uint32_t kbB = kk * 32 + ((lane >> 3) & 1) * 16;
            #pragma unroll
            for (int mi = 0; mi < 4; mi++)
                ldm4(af[mi], aH + (uint32_t)(mi * 16 + (lane & 15)) * ROWB + kbA);
            #pragma unroll
            for (int nb2 = 0; nb2 < 2; nb2++) {
                uint32_t rowb = wn + nb2 * 16 + (lane & 7) + ((lane >> 4) << 3);
                uint32_t r[4];
                ldm4(r, bH + rowb * ROWB + kbB);
                bfh[nb2 * 2][0] = r[0]; bfh[nb2 * 2][1] = r[1];
                bfh[nb2 * 2 + 1][0] = r[2]; bfh[nb2 * 2 + 1][1] = r[3];
            }
            #pragma unroll
            for (int mi = 0; mi < 4; mi++)
                #pragma unroll
                for (int nb = 0; nb < 4; nb++)
                    mma_bf16(acc[mi][nb], af[mi], bfh[nb]);
            // A-lo correction pass (reuses bfh)
            #pragma unroll
            for (int mi = 0; mi < 4; mi++)
                ldm4(af[mi], aH + AT + (uint32_t)(mi * 16 + (lane & 15)) * ROWB + kbA);
            #pragma unroll
            for (int mi = 0; mi < 4; mi++)
                #pragma unroll
                for (int nb = 0; nb < 4; nb++)
                    mma_bf16(acc[mi][nb], af[mi], bfh[nb]);
        }
    }

    int j = wid;                     // head index
    const float* asS = reinterpret_cast<const float*>(smem + SM_AS);
    const float* adS = reinterpret_cast<const float*>(smem + SM_AD);
    float asv[4][2], adv[4][2];
    #pragma unroll
    for (int nb = 0; nb < 4; nb++) {
        int col = wn + nb * 8 + (lane & 3) * 2;
        asv[nb][0] = asS[col];     asv[nb][1] = asS[col + 1];
        adv[nb][0] = adS[col];     adv[nb][1] = adS[col + 1];
    }

    #pragma unroll
    for (int mi = 0; mi < 4; mi++) {
        int row0 = m0 + mi * 16 + (lane >> 2);
        float s0 = 0.f, d0 = 0.f, s1 = 0.f, d1 = 0.f;
        #pragma unroll
        for (int nb = 0; nb < 4; nb++) {
            s0 += acc[mi][nb][0] * asv[nb][0] + acc[mi][nb][1] * asv[nb][1];
            d0 += acc[mi][nb][0] * adv[nb][0] + acc[mi][nb][1] * adv[nb][1];
            s1 += acc[mi][nb][2] * asv[nb][0] + acc[mi][nb][3] * asv[nb][1];
            d1 += acc[mi][nb][2] * adv[nb][0] + acc[mi][nb][3] * adv[nb][1];
        }
        #pragma unroll
        for (int o = 1; o < 4; o <<= 1) {
            s0 += __shfl_xor_sync(0xffffffffu, s0, o);
            d0 += __shfl_xor_sync(0xffffffffu, d0, o);
            s1 += __shfl_xor_sync(0xffffffffu, s1, o);
            d1 += __shfl_xor_sync(0xffffffffu, d1, o);
        }
        if ((lane & 3) == 0) {
            if (row0 < NN)     { g_as1[row0 * 8 + j] = s0;       g_ad1[row0 * 8 + j] = d0; }
            if (row0 + 8 < NN) { g_as1[(row0 + 8) * 8 + j] = s1; g_ad1[(row0 + 8) * 8 + j] = d1; }
        }
        #pragma unroll
        for (int nb = 0; nb < 4; nb++) {
            uint32_t gidx = (uint32_t)(wn >> 1) + nb * 4 + (lane & 3);
            __nv_bfloat162 p0 = __float22bfloat162_rn(make_float2(acc[mi][nb][0], acc[mi][nb][1]));
            __nv_bfloat162 p1 = __float22bfloat162_rn(make_float2(acc[mi][nb][2], acc[mi][nb][3]));
            if (row0 < NN)
                g_h1b[(size_t)row0 * 128 + gidx] = *reinterpret_cast<uint32_t*>(&p0);
            if (row0 + 8 < NN)
                g_h1b[(size_t)(row0 + 8) * 128 + gidx] = *reinterpret_cast<uint32_t*>(&p1);
        }
    }
}

// ---------------- layer-1 aggregation: branchless softmax, 4-edge batched -----
__global__ __launch_bounds__(256) void k_agg1(const float* __restrict__ b1) {
    int warp = (blockIdx.x * blockDim.x + threadIdx.x) >> 5;
    int lane = threadIdx.x & 31;
    if (warp >= NN) return;
    int d = warp;
    int s0 = g_rowstart[d], s1 = g_rowstart[d + 1];
    float adv = (lane < HH) ? g_ad1[d * HH + lane] : 0.f;
    int hs = lane >> 4;

    float den = 0.f;
    float2 acc[4];
    #pragma unroll
    for (int t = 0; t < 4; t++) acc[t] = make_float2(0.f, 0.f);

    int i = s0;
    for (; i + 4 <= s1; i += 4) {
        int e0 = g_csr[i], e1 = g_csr[i + 1], e2 = g_csr[i + 2], e3 = g_csr[i + 3];
        float p0 = 0.f, p1 = 0.f, p2 = 0.f, p3 = 0.f;
        if (lane < HH) {
            float v0 = g_as1[e0 * HH + lane] + adv;
            float v1 = g_as1[e1 * HH + lane] + adv;
            float v2 = g_as1[e2 * HH + lane] + adv;
            float v3 = g_as1[e3 * HH + lane] + adv;
            v0 = (v0 > 0.f) ? v0 : 0.2f * v0;  p0 = __expf(v0);
            v1 = (v1 > 0.f) ? v1 : 0.2f * v1;  p1 = __expf(v1);
            v2 = (v2 > 0.f) ? v2 : 0.2f * v2;  p2 = __expf(v2);
            v3 = (v3 > 0.f) ? v3 : 0.2f * v3;  p3 = __expf(v3);
            den += p0 + p1 + p2 + p3;
        }
        const uint32_t* r0 = g_h1b + (size_t)e0 * 128;
        const uint32_t* r1 = g_h1b + (size_t)e1 * 128;
        const uint32_t* r2 = g_h1b + (size_t)e2 * 128;
        const uint32_t* r3 = g_h1b + (size_t)e3 * 128;
        uint32_t u0[4], u1[4], u2[4], u3[4];
        #pragma unroll
        for (int t = 0; t < 4; t++) {
            u0[t] = r0[t * 32 + lane];
            u1[t] = r1[t * 32 + lane];
            u2[t] = r2[t * 32 + lane];
            u3[t] = r3[t * 32 + lane];
        }
        #pragma unroll
        for (int t = 0; t < 4; t++) {
            int sl = 2 * t + hs;
            float q0 = __shfl_sync(0xffffffffu, p0, sl);
            float q1 = __shfl_sync(0xffffffffu, p1, sl);
            float q2 = __shfl_sync(0xffffffffu, p2, sl);
            float q3 = __shfl_sync(0xffffffffu, p3, sl);
            float2 f0 = __bfloat1622float2(*reinterpret_cast<__nv_bfloat162*>(&u0[t]));
            float2 f1 = __bfloat1622float2(*reinterpret_cast<__nv_bfloat162*>(&u1[t]));
            float2 f2 = __bfloat1622float2(*reinterpret_cast<__nv_bfloat162*>(&u2[t]));
            float2 f3 = __bfloat1622float2(*reinterpret_cast<__nv_bfloat162*>(&u3[t]));
            acc[t].x += q0 * f0.x + q1 * f1.x + q2 * f2.x + q3 * f3.x;
            acc[t].y += q0 * f0.y + q1 * f1.y + q2 * f2.y + q3 * f3.y;
        }
    }
    for (; i < s1; i++) {
        int src = g_csr[i];
        float p = 0.f;
        if (lane < HH) {
            float v = g_as1[src * HH + lane] + adv;
            v = (v > 0.f) ? v : 0.2f * v;
            p = __expf(v);
            den += p;
        }
        const uint32_t* hr = g_h1b + (size_t)src * 128;
        #pragma unroll
        for (int t = 0; t < 4; t++) {
            float pj = __shfl_sync(0xffffffffu, p, 2 * t + hs);
            uint32_t u = hr[t * 32 + lane];
            float2 hf = __bfloat1622float2(*reinterpret_cast<__nv_bfloat162*>(&u));
            acc[t].x += pj * hf.x;
            acc[t].y += pj * hf.y;
        }
    }
    #pragma unroll
    for (int t = 0; t < 4; t++) {
        float dd = __shfl_sync(0xffffffffu, den, 2 * t + hs);
        float inv = 1.f / (dd + 1e-16f);
        int col = 64 * t + 2 * lane;
        float v0 = acc[t].x * inv + __ldg(b1 + col);
        float v1 = acc[t].y * inv + __ldg(b1 + col + 1);
        v0 = (v0 > 0.f) ? v0 : (__expf(v0) - 1.f);
        v1 = (v1 > 0.f) ? v1 : (__expf(v1) - 1.f);
        __nv_bfloat16 h0 = __float2bfloat16_rn(v0);
        __nv_bfloat16 h1 = __float2bfloat16_rn(v1);
        __nv_bfloat16 l0 = __float2bfloat16_rn(v0 - __bfloat162float(h0));
        __nv_bfloat16 l1 = __float2bfloat16_rn(v1 - __bfloat162float(h1));
        uint32_t wh = ((uint32_t)__bfloat16_as_ushort(h1) << 16) | __bfloat16_as_ushort(h0);
        uint32_t wl = ((uint32_t)__bfloat16_as_ushort(l1) << 16) | __bfloat16_as_ushort(l0);
        g_x2h[(size_t)d * 128 + 32 * t + lane] = wh;
        g_x2l[(size_t)d * 128 + 32 * t + lane] = wl;
    }
}

// ---------------- GEMM2: h2 = x2 @ W2 via bf16x2 (exact-A) HMMA + alpha2 ------
#define G2_ROWB 80
#define G2_AT   (128 * G2_ROWB)   // 10240
#define G2_BT   (48 * G2_ROWB)    // 3840
#define SM2_A(buf) ((buf) * 2 * G2_AT)
#define SM2_B(buf) (4 * G2_AT + (buf) * G2_BT)   // hi only
#define SM2_AS  (4 * G2_AT + 2 * G2_BT)          // 48640
#define SM2_AD  (SM2_AS + 256)
#define SM2_TOT (SM2_AD + 256)                   // 49152
#define G2_NCH 8   // K=256, chunks of 32

__global__ __launch_bounds__(256) void k_gemm2_mma(const float* __restrict__ a_src2,
                                                   const float* __restrict__ a_dst2) {
    extern __shared__ __align__(16) char smem[];
    uint32_t sbase = smem_u32(smem);

    int tid = threadIdx.x;
    int lane = tid & 31;
    int wid = tid >> 5;
    int wm = wid * 16;
    int m0 = blockIdx.x * 128;

    if (tid < NCLS) {
        *reinterpret_cast<float*>(smem + SM2_AS + tid * 4) = a_src2[tid];
        *reinterpret_cast<float*>(smem + SM2_AD + tid * 4) = a_dst2[tid];
    }

    float acc[5][4];
    #pragma unroll
    for (int nb = 0; nb < 5; nb++)
        #pragma unroll
        for (int q = 0; q < 4; q++) acc[nb][q] = 0.f;

    auto ldAB = [&](int buf, int kc) {
        #pragma unroll
        for (int i = 0; i < 4; i++) {
            int idx = tid + i * 256;
            int til = idx >> 9;
            int rem = idx & 511;
            int row = rem >> 2;
            int c   = rem & 3;
            if (m0 + row < NN) {
                const uint32_t* src = (til ? g_x2l : g_x2h) + (size_t)(m0 + row) * 128 + kc * 16 + c * 4;
                cp16(sbase + SM2_A(buf) + til * G2_AT + row * G2_ROWB + c * 16, src);
            }
        }
        // B hi only: 40 rows x 4 chunks = 160 cp16
        if (tid < 160) {
            int row = tid >> 2;
            int c   = tid & 3;
            const __nv_bfloat16* src = g_W2th + (size_t)row * 256 + kc * 32 + c * 8;
            cp16(sbase + SM2_B(buf) + row * G2_ROWB + c * 16, src);
        }
    };

    ldAB(0, 0);
    asm volatile("cp.async.commit_group;" ::: "memory");

    #pragma unroll 1
    for (int c = 0; c < G2_NCH; c++) {
        int buf = c & 1;
        if (c + 1 < G2_NCH) {
            ldAB(buf ^ 1, c + 1);
            asm volatile("cp.async.commit_group;" ::: "memory");
            asm volatile("cp.async.wait_group 1;" ::: "memory");
        } else {
            asm volatile("cp.async.wait_group 0;" ::: "memory");
        }
        __syncthreads();

        uint32_t aH = sbase + SM2_A(buf);
        uint32_t bH = sbase + SM2_B(buf);
        #pragma unroll
        for (int kk = 0; kk < 2; kk++) {
            uint32_t af[4], bfh[6][2];
            uint32_t kbA = kk * 32 + (lane >> 4) * 16;
            uint32_t kbB = kk * 32 + ((lane >> 3) & 1) * 16;
            ldm4(af, aH + (uint32_t)(wm + (lane & 15)) * G2_ROWB + kbA);
            #pragma unroll
            for (int g = 0; g < 3; g++) {
                uint32_t rowb = g * 16 + (lane & 7) + ((lane >> 4) << 3);
                uint32_t r[4];
                ldm4(r, bH + rowb * G2_ROWB + kbB);
                bfh[g * 2][0] = r[0]; bfh[g * 2][1] = r[1];
                bfh[g * 2 + 1][0] = r[2]; bfh[g * 2 + 1][1] = r[3];
            }
            #pragma unroll
            for (int nb = 0; nb < 5; nb++)
                mma_bf16(acc[nb], af, bfh[nb]);
            // A-lo correction pass
            ldm4(af, aH + G2_AT + (uint32_t)(wm + (lane & 15)) * G2_ROWB + kbA);
            #pragma unroll
            for (int nb = 0; nb < 5; nb++)
                mma_bf16(acc[nb], af, bfh[nb]);
        }
        __syncthreads();
    }

    const float* asS = reinterpret_cast<const float*>(smem + SM2_AS);
    const float* adS = reinterpret_cast<const float*>(smem + SM2_AD);
    float s0 = 0.f, d0 = 0.f, s1 = 0.f, d1 = 0.f;
    #pragma unroll
    for (int nb = 0; nb < 5; nb++) {
        int col = nb * 8 + (lane & 3) * 2;
        float a0 = asS[col], a1 = asS[col + 1];
        float q0 = adS[col], q1 = adS[col + 1];
        s0 += acc[nb][0] * a0 + acc[nb][1] * a1;
        d0 += acc[nb][0] * q0 + acc[nb][1] * q1;
        s1 += acc[nb][2] * a0 + acc[nb][3] * a1;
        d1 += acc[nb][2] * q0 + acc[nb][3] * q1;
    }
    #pragma unroll
    for (int o = 1; o < 4; o <<= 1) {
        s0 += __shfl_xor_sync(0xffffffffu, s0, o);
        d0 += __shfl_xor_sync(0xffffffffu, d0, o);
        s1 += __shfl_xor_sync(0xffffffffu, s1, o);
        d1 += __shfl_xor_sync(0xffffffffu, d1, o);
    }
    int r0 = m0 + wm + (lane >> 2);
    int r1 = r0 + 8;
    if ((lane & 3) == 0) {
        if (r0 < NN) { g_as2[r0] = s0; g_ad2[r0] = d0; }
        if (r1 < NN) { g_as2[r1] = s1; g_ad2[r1] = d1; }
    }
    #pragma unroll
    for (int nb = 0; nb < 5; nb++) {
        int col = nb * 8 + (lane & 3) * 2;
        if (r0 < NN)
            *reinterpret_cast<float2*>(g_h2 + (size_t)r0 * NCLS + col) = make_float2(acc[nb][0], acc[nb][1]);
        if (r1 < NN)
            *reinterpret_cast<float2*>(g_h2 + (size_t)r1 * NCLS + col) = make_float2(acc[nb][2], acc[nb][3]);
    }
}

// ---------------- layer-2 aggregation + log_softmax, 4-edge batched -----------
__global__ __launch_bounds__(256) void k_agg2(const float* __restrict__ b2,
                                              float* __restrict__ out) {
    int warp = (blockIdx.x * blockDim.x + threadIdx.x) >> 5;
    int lane = threadIdx.x & 31;
    if (warp >= NN) return;
    int d = warp;
    int s0 = g_rowstart[d], s1 = g_rowstart[d + 1];
    float adv = g_ad2[d];

    float den = 0.f, a0 = 0.f, a1 = 0.f;
    int i = s0;
    for (; i + 4 <= s1; i += 4) {
        int e0 = g_csr[i], e1 = g_csr[i + 1], e2 = g_csr[i + 2], e3 = g_csr[i + 3];
        float v0 = g_as2[e0] + adv, v1 = g_as2[e1] + adv;
        float v2 = g_as2[e2] + adv, v3 = g_as2[e3] + adv;
        v0 = (v0 > 0.f) ? v0 : 0.2f * v0;  float p0 = __expf(v0);
        v1 = (v1 > 0.f) ? v1 : 0.2f * v1;  float p1 = __expf(v1);
        v2 = (v2 > 0.f) ? v2 : 0.2f * v2;  float p2 = __expf(v2);
        v3 = (v3 > 0.f) ? v3 : 0.2f * v3;  float p3 = __expf(v3);
        den += p0 + p1 + p2 + p3;
        const float* r0 = g_h2 + (size_t)e0 * NCLS;
        const float* r1 = g_h2 + (size_t)e1 * NCLS;
        const float* r2 = g_h2 + (size_t)e2 * NCLS;
        const float* r3 = g_h2 + (size_t)e3 * NCLS;
        float h00 = r0[lane], h01 = r0[32 + lane];
        float h10 = r1[lane], h11 = r1[32 + lane];
        float h20 = r2[lane], h21 = r2[32 + lane];
        float h30 = r3[lane], h31 = r3[32 + lane];
        a0 += p0 * h00 + p1 * h10 + p2 * h20 + p3 * h30;
        a1 += p0 * h01 + p1 * h11 + p2 * h21 + p3 * h31;
    }
    for (; i < s1; i++) {
        int src = g_csr[i];
        float v = g_as2[src] + adv;
        float e = (v > 0.f) ? v : 0.2f * v;
        float p = __expf(e);
        den += p;
        const float* hr = g_h2 + (size_t)src * NCLS;
        a0 += p * hr[lane];
        a1 += p * hr[32 + lane];
    }
    float inv = 1.f / (den + 1e-16f);
    float v0 = a0 * inv + b2[lane];
    float v1 = -3.0e38f;
    if (lane < 8) v1 = a1 * inv + b2[32 + lane];

    float mx = fmaxf(v0, v1);
    #pragma unroll
    for (int o = 16; o; o >>= 1) mx = fmaxf(mx, __shfl_xor_sync(0xffffffffu, mx, o));
    float se = __expf(v0 - mx) + ((lane < 8) ? __expf(v1 - mx) : 0.f);
    #pragma unroll
    for (int o = 16; o; o >>= 1) se += __shfl_xor_sync(0xffffffffu, se, o);
    float lse = mx + __logf(se);

    out[(size_t)d * NCLS + lane] = v0 - lse;
    if (lane < 8) out[(size_t)d * NCLS + 32 + lane] = v1 - lse;
}

// ---------------- launch ----------------
extern "C" void kernel_launch(void* const* d_in, const int* in_sizes, int n_in,
                              void* d_out, int out_size) {
    const float* x       = (const float*)d_in[0];
    const int*   ei      = (const int*)  d_in[1];
    const float* W1      = (const float*)d_in[2];
    const float* a_src1  = (const float*)d_in[3];
    const float* a_dst1  = (const float*)d_in[4];
    const float* b1      = (const float*)d_in[5];
    const float* W2      = (const float*)d_in[6];
    const float* a_src2  = (const float*)d_in[7];
    const float* a_dst2  = (const float*)d_in[8];
    const float* b2      = (const float*)d_in[9];
    float* out = (float*)d_out;

    cudaFuncSetAttribute(k_gemm1_mma, cudaFuncAttributeMaxDynamicSharedMemorySize, SM_TOT);
    cudaFuncSetAttribute(k_gemm2_mma, cudaFuncAttributeMaxDynamicSharedMemorySize, SM2_TOT);

    // order chosen so the profiled launch slot (#4) is gemm1
    k_split_w<<<(HC * FIN + 255) / 256, 256>>>(W1);                          // 1
    k_zero_deg<<<(NN + 255) / 256, 256>>>();                                 // 2
    k_count<<<(ET + 255) / 256, 256>>>(ei);                                  // 3
    k_gemm1_mma<<<MPAD / 64, 256, SM_TOT>>>(x, a_src1, a_dst1);              // 4
    k_split_w2<<<(40 * 256 + 255) / 256, 256>>>(W2);                         // 5
    k_scan<<<1, 1024>>>();                                                   // 6
    k_scatter<<<(ET + 255) / 256, 256>>>(ei);                                // 7
    k_agg1<<<(NN * 32 + 255) / 256, 256>>>(b1);                              // 8
    k_gemm2_mma<<<MPAD / 128, 256, SM2_TOT>>>(a_src2, a_dst2);               // 9
    k_agg2<<<(NN * 32 + 255) / 256, 256>>>(b2, out);                         // 10
}